// round 5
// baseline (speedup 1.0000x reference)
#include <cuda_runtime.h>
#include <cstddef>

// Problem constants: B=1, F=12, C=128, H=W=256, pad=1.
#define H_IN 256
#define W_IN 256
#define CH   128
#define H_OUT 258
#define W_OUT 258
#define PLANE_IN  (H_IN * W_IN)     // 65536
#define PLANE_OUT (H_OUT * W_OUT)   // 66564

// ---------------------------------------------------------------------------
// Fully fused: interior copy + halo edge scatter + corner scatter, one kernel.
// Each thread: one input float4 (aligned load), 4 scalar stores to shifted
// interior position. Boundary threads additionally scatter their edge values
// into neighbor-face halo slots; corner threads (i in {0,255} AND j4 in
// {0,63}) also write the corner pixels they uniquely source (equatorial
// 2-point averages fetch the partner pixel with one extra load).
// ---------------------------------------------------------------------------
__global__ void hp_main(const float* __restrict__ in, float* __restrict__ out) {
    int idx = blockIdx.x * blockDim.x + threadIdx.x;   // float4 index
    int plane = idx >> 14;            // 16384 float4 per plane
    int rem   = idx & 16383;
    int i     = rem >> 6;             // 64 float4 per row
    int j4    = rem & 63;

    float4 v = reinterpret_cast<const float4*>(in)[idx];
    {
        float* o = out + (size_t)plane * PLANE_OUT + (size_t)(i + 1) * W_OUT + (j4 * 4 + 1);
        o[0] = v.x; o[1] = v.y; o[2] = v.z; o[3] = v.w;
    }

    const bool bi = (i == 0) | (i == H_IN - 1);
    const bool bj = (j4 == 0) | (j4 == 63);
    if (!(bi | bj)) return;            // fast exit for interior threads (~97%)

    const int face = plane >> 7;
    const int ch   = plane & (CH - 1);
    const int gg   = face >> 2;       // 0=north, 1=equatorial, 2=south
    const int fi   = face & 3;
    const int j    = j4 * 4;          // src column of v.x

    auto dbase = [&](int df) -> float* {
        return out + ((size_t)df * CH + ch) * PLANE_OUT;
    };
    const size_t ROW_BOT = (size_t)(H_OUT - 1) * W_OUT;   // row 257 offset
    const int    COL_R   = W_OUT - 1;                      // col 257
    const size_t TL = 0, TR = (size_t)COL_R, BL = ROW_BOT, BR = ROW_BOT + COL_R;

    // ---- edge scatter (same map as R4, verified) ----
    if (gg == 0) {                       // northern source faces 0-3
        if (i == 0) {                    // -> face (fi+1)&3, col0, rows j+1..j+4
            float* d = dbase((fi + 1) & 3);
            d[(size_t)(j + 1) * W_OUT] = v.x;
            d[(size_t)(j + 2) * W_OUT] = v.y;
            d[(size_t)(j + 3) * W_OUT] = v.z;
            d[(size_t)(j + 4) * W_OUT] = v.w;
        }
        if (i == H_IN - 1) {             // -> face 4+fi, row0, cols j+1..
            float* d = dbase(4 + fi);
            d[j + 1] = v.x; d[j + 2] = v.y; d[j + 3] = v.z; d[j + 4] = v.w;
        }
        if (j4 == 0)                     // (i,0) -> face (fi+3)&3, row0 col i+1
            dbase((fi + 3) & 3)[i + 1] = v.x;
        if (j4 == 63)                    // (i,255) -> face 4+((fi+1)&3), col0 row i+1
            dbase(4 + ((fi + 1) & 3))[(size_t)(i + 1) * W_OUT] = v.w;
    } else if (gg == 1) {                // equatorial source faces 4-7
        if (i == 0) {                    // -> face fi, row257, cols j+1..
            float* d = dbase(fi) + ROW_BOT;
            d[j + 1] = v.x; d[j + 2] = v.y; d[j + 3] = v.z; d[j + 4] = v.w;
        }
        if (i == H_IN - 1) {             // -> face 8+((fi+3)&3), row0, cols j+1..
            float* d = dbase(8 + ((fi + 3) & 3));
            d[j + 1] = v.x; d[j + 2] = v.y; d[j + 3] = v.z; d[j + 4] = v.w;
        }
        if (j4 == 0)                     // (i,0) -> face (fi+3)&3, col257 row i+1
            dbase((fi + 3) & 3)[(size_t)(i + 1) * W_OUT + COL_R] = v.x;
        if (j4 == 63)                    // (i,255) -> face 8+fi, col0 row i+1
            dbase(8 + fi)[(size_t)(i + 1) * W_OUT] = v.w;
    } else {                             // southern source faces 8-11
        if (i == 0) {                    // -> face 4+fi, row257, cols j+1..
            float* d = dbase(4 + fi) + ROW_BOT;
            d[j + 1] = v.x; d[j + 2] = v.y; d[j + 3] = v.z; d[j + 4] = v.w;
        }
        if (i == H_IN - 1) {             // -> face 8+((fi+3)&3), col257, rows j+1..
            float* d = dbase(8 + ((fi + 3) & 3)) + COL_R;
            d[(size_t)(j + 1) * W_OUT] = v.x;
            d[(size_t)(j + 2) * W_OUT] = v.y;
            d[(size_t)(j + 3) * W_OUT] = v.z;
            d[(size_t)(j + 4) * W_OUT] = v.w;
        }
        if (j4 == 0)                     // (i,0) -> face 4+((fi+1)&3), col257 row i+1
            dbase(4 + ((fi + 1) & 3))[(size_t)(i + 1) * W_OUT + COL_R] = v.x;
        if (j4 == 63)                    // (i,255) -> face 8+((fi+1)&3), row257 col i+1
            dbase(8 + ((fi + 1) & 3))[ROW_BOT + i + 1] = v.w;
    }

    // ---- corner scatter ----
    if (bi & bj) {
        if (gg == 0) {                   // north source face fi
            if (i == 0 && j4 == 0) {     // pixel (0,0) = v.x
                dbase((fi + 2) & 3)[TL] = v.x;   // tl of north dest (fi+2)&3
                dbase((fi + 3) & 3)[TR] = v.x;   // tr of north dest (fi+3)&3
            } else if (i == 0) {         // pixel (0,255) = v.w
                dbase((fi + 1) & 3)[BL] = v.w;   // bl of north dest (fi+1)&3
            } else if (j4 == 0) {        // pixel (255,0) = v.x
                // tl of equatorial dest fi = 0.5*this + 0.5*north[(fi+3)&3][0,255]
                float other = in[((size_t)((fi + 3) & 3) * CH + ch) * PLANE_IN + (W_IN - 1)];
                dbase(4 + fi)[TL] = 0.5f * v.x + 0.5f * other;
            } else {                     // pixel (255,255) = v.w
                dbase(8 + fi)[TL] = v.w;         // tl of south dest 8+fi
            }
        } else if (gg == 1) {            // equatorial source face 4+fi
            if (i == H_IN - 1 && j4 == 0)        // pixel (255,0) = v.x
                dbase(4 + ((fi + 3) & 3))[TR] = v.x;  // tr of equat dest 4+((fi+3)&3)
            if (i == 0 && j4 == 63)              // pixel (0,255) = v.w
                dbase(4 + ((fi + 1) & 3))[BL] = v.w;  // bl of equat dest 4+((fi+1)&3)
        } else {                         // south source face 8+fi
            if (i == 0 && j4 == 0) {     // pixel (0,0) = v.x
                dbase(fi)[BR] = v.x;             // br of north dest fi
            } else if (i == 0) {         // pixel (0,255) = v.w
                // br of equatorial dest fi = 0.5*this + 0.5*south[8+((fi+3)&3)][255,0]
                float other = in[((size_t)(8 + ((fi + 3) & 3)) * CH + ch) * PLANE_IN
                                 + (size_t)(H_IN - 1) * W_IN];
                dbase(4 + fi)[BR] = 0.5f * v.w + 0.5f * other;
            } else if (j4 == 63) {       // pixel (255,255) = v.w
                dbase(8 + ((fi + 3) & 3))[TR] = v.w;  // tr of south dest 8+((fi+3)&3)
                dbase(8 + ((fi + 1) & 3))[BL] = v.w;  // bl of south dest 8+((fi+1)&3)
                dbase(8 + ((fi + 2) & 3))[BR] = v.w;  // br of south dest 8+((fi+2)&3)
            }
        }
    }
}

extern "C" void kernel_launch(void* const* d_in, const int* in_sizes, int n_in,
                              void* d_out, int out_size) {
    const float* x = (const float*)d_in[0];
    float* out = (float*)d_out;

    const int n_in_elems = in_sizes[0];          // B*12*C*H*W
    const int TPB = 256;
    const int n_f4 = n_in_elems / 4;
    hp_main<<<n_f4 / TPB, TPB>>>(x, out);

    (void)n_in; (void)out_size;
}